// round 17
// baseline (speedup 1.0000x reference)
#include <cuda_runtime.h>
#include <float.h>

// _VQ_29609504538631 : fused VQ-VAE bottleneck
// R16 = R15 with structural friction removed (math byte-identical):
//   - codebook gets its own smem buffer (dynamic smem 109KB, 2 CTAs/SM):
//     cb+norm staging moves to phase 0, one barrier eliminated (6 -> 5)
//   - exch / cand transposed to [row][slice*NP+pr]: merge + rescore LDS
//     now conflict-free (was 32-way conflicted, ~1K crossbar cyc/warp)
//   - out_w staged via float4 (coalesced LDG.128 + STS.128)

namespace {
constexpr int Bb = 8;
constexpr int Cc = 1024;
constexpr int Tt = 8192;
constexpr int Kk = 1024;
constexpr int Dd = 8;
constexpr int TT  = 256;              // tokens per block (128 pairs)
constexpr int NP  = 128;              // token-pairs per block
constexpr int NT  = 256;              // threads per block
constexpr int CH  = 512;              // channels per phase-1 slice
constexpr int KH  = 512;              // codes per phase-2 slice
constexpr int CHUNK = 64;             // fp32 accumulation chunk (validated)
// phase-3 quad mapping
constexpr int QD  = 64;               // quads per block
constexpr int CH3 = 256;              // channels per phase-3 slice
// dynamic smem layout (bytes)
constexpr int OFF_BUF  = 0;           // float[8192]: in_w^T, later out_w
constexpr int OFF_CBB  = 32768;       // float[8192]: codebook (whole kernel)
constexpr int OFF_AUX  = 65536;       // u64[1024]: (-0.5||w||^2,0) -> (out_b,0)
constexpr int OFF_EXCH = 73728;       // double[16][256]: [tok*8+d][slice*128+pr]
constexpr int OFF_CAND = 106496;      // int[4][256]: [tok*2+j][slice*128+pr]
constexpr int OFF_IBUF = 110592;      // int[256]: winning ids
constexpr int OFF_BIAS = 111616;      // float[8]
constexpr int SMEM_BYTES = 111680;
}

typedef unsigned long long u64;

__device__ __forceinline__ u64 pk2(float lo, float hi) {
    u64 r; asm("mov.b64 %0, {%1,%2};" : "=l"(r) : "f"(lo), "f"(hi)); return r;
}
__device__ __forceinline__ void upk2(u64 v, float& lo, float& hi) {
    asm("mov.b64 {%0,%1}, %2;" : "=f"(lo), "=f"(hi) : "l"(v));
}
__device__ __forceinline__ u64 ffma2(u64 a, u64 b, u64 c) {
    u64 r; asm("fma.rn.f32x2 %0, %1, %2, %3;" : "=l"(r) : "l"(a), "l"(b), "l"(c)); return r;
}

__global__ __launch_bounds__(NT, 2) void vq_fused(
    const float* __restrict__ z,
    const float* __restrict__ in_w,    // [D, C]
    const float* __restrict__ in_b,    // [D]
    const float* __restrict__ cb,      // [K, D]
    const float* __restrict__ out_w,   // [C, D]
    const float* __restrict__ out_b,   // [C]
    float* __restrict__ out,           // [B, C, T]
    float* __restrict__ ids_out)       // [B, T] (as float), may be null
{
    extern __shared__ __align__(16) char smem[];
    float*  buf     = reinterpret_cast<float*>(smem + OFF_BUF);
    float*  cbb     = reinterpret_cast<float*>(smem + OFF_CBB);
    u64*    aux2    = reinterpret_cast<u64*>(smem + OFF_AUX);
    double* exch    = reinterpret_cast<double*>(smem + OFF_EXCH);
    int*    cand    = reinterpret_cast<int*>(smem + OFF_CAND);
    int*    ibuf    = reinterpret_cast<int*>(smem + OFF_IBUF);
    float*  bias_in = reinterpret_cast<float*>(smem + OFF_BIAS);

    const int tid   = threadIdx.x;
    const int slice = tid >> 7;           // 0/1 (phases 1-2)
    const int pr    = tid & (NP - 1);     // pair index
    const int col   = slice * NP + pr;    // transposed exch/cand column
    const int b     = blockIdx.x / (Tt / TT);
    const int tbase = (blockIdx.x % (Tt / TT)) * TT;
    const int t0    = tbase + 2 * pr;     // even
    // phase-3 quad mapping
    const int slc3  = tid >> 6;           // 0..3
    const int quad  = tid & (QD - 1);
    const int tq0   = tbase + 4 * quad;

    // ---- Phase 0: stage in_w^T -> buf, codebook -> cbb + norms -> aux2
    for (int i = tid; i < Dd * Cc; i += NT) {
        int d = i & 7, c = i >> 3;
        buf[i] = in_w[d * Cc + c];        // scattered LDG, conflict-free STS
    }
    for (int k = tid; k < Kk; k += NT) {
        float4 c0 = __ldg(reinterpret_cast<const float4*>(cb + k * 8));
        float4 c1 = __ldg(reinterpret_cast<const float4*>(cb + k * 8) + 1);
        reinterpret_cast<float4*>(cbb)[k * 2]     = c0;
        reinterpret_cast<float4*>(cbb)[k * 2 + 1] = c1;
        double n = (double)c0.x*c0.x + (double)c0.y*c0.y
                 + (double)c0.z*c0.z + (double)c0.w*c0.w
                 + (double)c1.x*c1.x + (double)c1.y*c1.y
                 + (double)c1.z*c1.z + (double)c1.w*c1.w;
        aux2[k] = pk2(-(float)(0.5 * n), 0.0f);
    }
    if (tid < Dd) bias_in[tid] = in_b[tid];
    __syncthreads();                                   // barrier 1

    // ---- Phase 1: partial e over this slice's 512 channels, 2 tokens packed.
    double p0[Dd], p1[Dd];
    #pragma unroll
    for (int d = 0; d < Dd; d++) { p0[d] = 0.0; p1[d] = 0.0; }

    const float* zp = z + (size_t)b * Cc * Tt + t0;
    const int cbeg = slice * CH;
    for (int c0 = cbeg; c0 < cbeg + CH; c0 += CHUNK) {
        u64 a0[4], a1[4];
        #pragma unroll
        for (int j = 0; j < 4; j++) { a0[j] = 0ull; a1[j] = 0ull; }
        #pragma unroll 16
        for (int cc = 0; cc < CHUNK; cc++) {
            int c = c0 + cc;
            float2 v2 = __ldg(reinterpret_cast<const float2*>(zp + (size_t)c * Tt));
            u64 v0 = pk2(v2.x, v2.x);
            u64 v1 = pk2(v2.y, v2.y);
            const ulonglong2* wp = reinterpret_cast<const ulonglong2*>(buf + c * 8);
            ulonglong2 wA = wp[0];
            ulonglong2 wB = wp[1];
            a0[0] = ffma2(v0, wA.x, a0[0]);
            a0[1] = ffma2(v0, wA.y, a0[1]);
            a0[2] = ffma2(v0, wB.x, a0[2]);
            a0[3] = ffma2(v0, wB.y, a0[3]);
            a1[0] = ffma2(v1, wA.x, a1[0]);
            a1[1] = ffma2(v1, wA.y, a1[1]);
            a1[2] = ffma2(v1, wB.x, a1[2]);
            a1[3] = ffma2(v1, wB.y, a1[3]);
        }
        #pragma unroll
        for (int j = 0; j < 4; j++) {
            float lo, hi;
            upk2(a0[j], lo, hi); p0[2*j] += (double)lo; p0[2*j+1] += (double)hi;
            upk2(a1[j], lo, hi); p1[2*j] += (double)lo; p1[2*j+1] += (double)hi;
        }
    }
    // publish partials (transposed: row = tok*8+d, col = slice*NP+pr)
    #pragma unroll
    for (int d = 0; d < Dd; d++) {
        exch[(0 * Dd + d) * NT + col] = p0[d];
        exch[(1 * Dd + d) * NT + col] = p1[d];
    }
    __syncthreads();                                   // barrier 2

    // merge partials in identical order (s0 + s1) + bias, both slice threads
    float e0[Dd], e1[Dd];
    #pragma unroll
    for (int d = 0; d < Dd; d++) {
        double s0 = exch[(0 * Dd + d) * NT + pr] + exch[(0 * Dd + d) * NT + NP + pr];
        double s1 = exch[(1 * Dd + d) * NT + pr] + exch[(1 * Dd + d) * NT + NP + pr];
        e0[d] = (float)(s0 + (double)bias_in[d]);
        e1[d] = (float)(s1 + (double)bias_in[d]);
    }

    // ---- Phase 2b: scan this slice's 512 codes in groups of 4, both tokens.
    u64 ep0[4], ep1[4];
    #pragma unroll
    for (int j = 0; j < 4; j++) {
        ep0[j] = pk2(e0[2*j], e0[2*j+1]);
        ep1[j] = pk2(e1[2*j], e1[2*j+1]);
    }
    float b1t0 = -FLT_MAX, b2t0 = -FLT_MAX, b1t1 = -FLT_MAX, b2t1 = -FLT_MAX;
    int   i1t0 = slice*KH, i2t0 = slice*KH, i1t1 = slice*KH, i2t1 = slice*KH;
    const int kbeg = slice * KH;
    #pragma unroll 2
    for (int k = kbeg; k < kbeg + KH; k += 4) {
        const ulonglong2* wp = reinterpret_cast<const ulonglong2*>(cbb + k * 8);
        ulonglong2 iab01 = *reinterpret_cast<const ulonglong2*>(&aux2[k]);
        ulonglong2 iab23 = *reinterpret_cast<const ulonglong2*>(&aux2[k + 2]);

        // codes k, k+1
        ulonglong2 wa0 = wp[0], wa1 = wp[1];
        ulonglong2 wb0 = wp[2], wb1 = wp[3];
        u64 da = ffma2(ep0[3], wa1.y, ffma2(ep0[2], wa1.x,
                 ffma2(ep0[1], wa0.y, ffma2(ep0[0], wa0.x, iab01.x))));
        u64 db = ffma2(ep0[3], wb1.y, ffma2(ep0[2], wb1.x,
                 ffma2(ep0[1], wb0.y, ffma2(ep0[0], wb0.x, iab01.y))));
        float lo, hi;
        upk2(da, lo, hi); float sa0 = lo + hi;
        upk2(db, lo, hi); float sb0 = lo + hi;
        da = ffma2(ep1[3], wa1.y, ffma2(ep1[2], wa1.x,
             ffma2(ep1[1], wa0.y, ffma2(ep1[0], wa0.x, iab01.x))));
        db = ffma2(ep1[3], wb1.y, ffma2(ep1[2], wb1.x,
             ffma2(ep1[1], wb0.y, ffma2(ep1[0], wb0.x, iab01.y))));
        upk2(da, lo, hi); float sa1 = lo + hi;
        upk2(db, lo, hi); float sb1 = lo + hi;

        bool pa0 = sa0 >= sb0;
        float s01_0 = pa0 ? sa0 : sb0;  int k01_0 = pa0 ? k : k + 1;
        bool pa1 = sa1 >= sb1;
        float s01_1 = pa1 ? sa1 : sb1;  int k01_1 = pa1 ? k : k + 1;

        // codes k+2, k+3 (reuse w registers)
        wa0 = wp[4]; wa1 = wp[5];
        wb0 = wp[6]; wb1 = wp[7];
        da = ffma2(ep0[3], wa1.y, ffma2(ep0[2], wa1.x,
             ffma2(ep0[1], wa0.y, ffma2(ep0[0], wa0.x, iab23.x))));
        db = ffma2(ep0[3], wb1.y, ffma2(ep0[2], wb1.x,
             ffma2(ep0[1], wb0.y, ffma2(ep0[0], wb0.x, iab23.y))));
        upk2(da, lo, hi); float sc0 = lo + hi;
        upk2(db, lo, hi); float sd0 = lo + hi;
        da = ffma2(ep1[3], wa1.y, ffma2(ep1[2], wa1.x,
             ffma2(ep1[1], wa0.y, ffma2(ep1[0], wa0.x, iab23.x))));
        db = ffma2(ep1[3], wb1.y, ffma2(ep1[2], wb1.x,
             ffma2(ep1[1], wb0.y, ffma2(ep1[0], wb0.x, iab23.y))));
        upk2(da, lo, hi); float sc1 = lo + hi;
        upk2(db, lo, hi); float sd1 = lo + hi;

        bool pb0 = sc0 >= sd0;
        float s23_0 = pb0 ? sc0 : sd0;  int k23_0 = pb0 ? k + 2 : k + 3;
        bool pb1 = sc1 >= sd1;
        float s23_1 = pb1 ? sc1 : sd1;  int k23_1 = pb1 ? k + 2 : k + 3;

        bool pc0 = s01_0 >= s23_0;
        float sm0 = pc0 ? s01_0 : s23_0;  int km0 = pc0 ? k01_0 : k23_0;
        bool pc1 = s01_1 >= s23_1;
        float sm1 = pc1 ? s01_1 : s23_1;  int km1 = pc1 ? k01_1 : k23_1;

        {
            bool q2 = sm0 > b2t0;
            float c2 = q2 ? sm0 : b2t0;  int j2 = q2 ? km0 : i2t0;
            bool q1 = sm0 > b1t0;
            b2t0 = q1 ? b1t0 : c2;       i2t0 = q1 ? i1t0 : j2;
            b1t0 = q1 ? sm0 : b1t0;      i1t0 = q1 ? km0 : i1t0;
        }
        {
            bool q2 = sm1 > b2t1;
            float c2 = q2 ? sm1 : b2t1;  int j2 = q2 ? km1 : i2t1;
            bool q1 = sm1 > b1t1;
            b2t1 = q1 ? b1t1 : c2;       i2t1 = q1 ? i1t1 : j2;
            b1t1 = q1 ? sm1 : b1t1;      i1t1 = q1 ? km1 : i1t1;
        }
    }
    // publish candidates (transposed, conflict-free)
    cand[0 * NT + col] = i1t0;   // tok0 j0
    cand[1 * NT + col] = i2t0;   // tok0 j1
    cand[2 * NT + col] = i1t1;   // tok1 j0
    cand[3 * NT + col] = i2t1;   // tok1 j1
    __syncthreads();                                   // barrier 3

    // ---- fp64 rescore of all 4 candidates per token; lowest index on ties.
    int bi0 = 0, bi1 = 0;
    #pragma unroll
    for (int tk = 0; tk < 2; tk++) {
        const float* ee = tk ? e1 : e0;
        double bscore = -DBL_MAX;
        int    bidx   = Kk;
        #pragma unroll
        for (int j = 0; j < 4; j++) {
            int kc = cand[(tk * 2 + (j & 1)) * NT + (j >> 1) * NP + pr];
            const float* w = cbb + kc * 8;
            double dot = 0.0, nrm = 0.0;
            #pragma unroll
            for (int i = 0; i < Dd; i++) {
                double wi = (double)w[i];
                dot += (double)ee[i] * wi;
                nrm += wi * wi;
            }
            double sc = dot - 0.5 * nrm;
            if (sc > bscore || (sc == bscore && kc < bidx)) {
                bscore = sc; bidx = kc;
            }
        }
        if (tk) bi1 = bidx; else bi0 = bidx;
    }

    // publish ids
    if (slice == 0) {
        ibuf[2 * pr]     = bi0;
        ibuf[2 * pr + 1] = bi1;
    }
    __syncthreads();                                   // barrier 4

    // quad threads grab their 4 codes (cbb stays resident); stage out_w/out_b
    int myid[4];
    u64 qp[4][4];
    #pragma unroll
    for (int tk = 0; tk < 4; tk++) {
        myid[tk] = ibuf[4 * quad + tk];
        const ulonglong2* w = reinterpret_cast<const ulonglong2*>(cbb + myid[tk] * 8);
        ulonglong2 x0 = w[0], x1 = w[1];
        qp[tk][0] = x0.x; qp[tk][1] = x0.y; qp[tk][2] = x1.x; qp[tk][3] = x1.y;
    }
    // out_w -> buf via float4 (in_w dead since phase 1); out_b -> aux2
    for (int i4 = tid; i4 < (Cc * Dd) / 4; i4 += NT)
        reinterpret_cast<float4*>(buf)[i4] =
            __ldg(reinterpret_cast<const float4*>(out_w) + i4);
    for (int i = tid; i < Cc; i += NT) aux2[i] = pk2(out_b[i], 0.0f);
    __syncthreads();                                   // barrier 5

    // ---- Phase 3b: quad mapping — 4 tokens, channels [slc3*256, +256).
    float* op = out + (size_t)b * Cc * Tt + tq0;
    const int cbeg3 = slc3 * CH3;
    #pragma unroll 4
    for (int c = cbeg3; c < cbeg3 + CH3; c++) {
        const ulonglong2* wp = reinterpret_cast<const ulonglong2*>(buf + c * 8);
        ulonglong2 wA = wp[0], wB = wp[1];
        u64 ic = aux2[c];
        float s[4];
        #pragma unroll
        for (int tk = 0; tk < 4; tk++) {
            u64 dd = ffma2(qp[tk][3], wB.y, ffma2(qp[tk][2], wB.x,
                     ffma2(qp[tk][1], wA.y, ffma2(qp[tk][0], wA.x, ic))));
            float lo, hi;
            upk2(dd, lo, hi);
            s[tk] = lo + hi;
        }
        *reinterpret_cast<float4*>(op + (size_t)c * Tt) =
            make_float4(s[0], s[1], s[2], s[3]);
    }

    if (slc3 == 0 && ids_out) {
        *reinterpret_cast<float4*>(ids_out + (size_t)b * Tt + tq0) =
            make_float4((float)myid[0], (float)myid[1],
                        (float)myid[2], (float)myid[3]);
    }
}

extern "C" void kernel_launch(void* const* d_in, const int* in_sizes, int n_in,
                              void* d_out, int out_size) {
    const float* z     = (const float*)d_in[0];
    const float* in_w  = (const float*)d_in[1];
    const float* in_b  = (const float*)d_in[2];
    const float* cb    = (const float*)d_in[3];
    const float* out_w = (const float*)d_in[4];
    const float* out_b = (const float*)d_in[5];

    float* out = (float*)d_out;
    const long long out_elems = (long long)Bb * Cc * Tt;
    float* ids = (out_size > out_elems) ? out + out_elems : nullptr;

    cudaFuncSetAttribute(vq_fused,
                         cudaFuncAttributeMaxDynamicSharedMemorySize, SMEM_BYTES);
    dim3 grid(Bb * (Tt / TT));   // 256 blocks x 256 threads
    vq_fused<<<grid, NT, SMEM_BYTES>>>(z, in_w, in_b, cb, out_w, out_b, out, ids);
}